// round 3
// baseline (speedup 1.0000x reference)
#include <cuda_runtime.h>

// ---------------------------------------------------------------------------
// SwinIR-lite forward: conv3x3(3->60) -> 36 x [LN+WindowAttn+res, LN+MLP+res]
// -> conv3x3(60->12) + PixelShuffle(2).  All fp32.  B=2, H=W=128, C=60.
// ---------------------------------------------------------------------------

constexpr int Bn   = 2;
constexpr int Hc   = 128;
constexpr int Wc   = 128;
constexpr int Cch  = 60;
constexpr int NHEADS = 3;
constexpr int NTOK = Bn * Hc * Wc;          // 32768 tokens
constexpr int QKVC = 180;
constexpr int FCC  = 120;
constexpr int NL   = 36;

// Scratch (device globals; no allocation allowed)
__device__ float g_feat[NTOK * Cch];        // 7.5 MB
__device__ float g_qkv [NTOK * QKVC];       // 22.5 MB
__device__ float g_attn[NTOK * Cch];        // 7.5 MB
__device__ float g_mlp [NTOK * FCC];        // 15 MB

// ---------------------------------------------------------------------------
// conv3x3 3->60, NCHW in -> NHWC (token-major) out
// ---------------------------------------------------------------------------
__global__ __launch_bounds__(256) void conv_in_k(
    const float* __restrict__ x, const float* __restrict__ w,
    const float* __restrict__ b)
{
    int idx = blockIdx.x * blockDim.x + threadIdx.x;
    if (idx >= NTOK * Cch) return;
    int co = idx % Cch;
    int p  = idx / Cch;
    int wx = p % Wc;
    int hy = (p / Wc) % Hc;
    int bb = p / (Wc * Hc);
    float acc = b[co];
#pragma unroll
    for (int ci = 0; ci < 3; ci++) {
#pragma unroll
        for (int kh = 0; kh < 3; kh++) {
            int hh = hy + kh - 1;
            if ((unsigned)hh >= (unsigned)Hc) continue;
#pragma unroll
            for (int kw = 0; kw < 3; kw++) {
                int ww2 = wx + kw - 1;
                if ((unsigned)ww2 >= (unsigned)Wc) continue;
                acc += x[((bb * 3 + ci) * Hc + hh) * Wc + ww2] *
                       w[((co * 3 + ci) * 3 + kh) * 3 + kw];
            }
        }
    }
    g_feat[idx] = acc;
}

// ---------------------------------------------------------------------------
// LN (over K=60) + GEMM [T,K]@[K,N] + bias (+ optional Swish).
// Block: NP*MG threads; tile TM tokens.  x-tile stored k-major -> float4 loads.
// OUT_MLP=false -> g_qkv, true -> g_mlp.
// ---------------------------------------------------------------------------
template <int K, int N, int NP, int MG, int TM, bool SWISH, bool OUT_MLP>
__global__ __launch_bounds__(NP * MG) void ln_gemm_k(
    const float* __restrict__ gamma, const float* __restrict__ beta,
    const float* __restrict__ w, const float* __restrict__ bias)
{
    extern __shared__ float sm[];
    float* ws = sm;              // K*N
    float* bs = sm + K * N;      // N
    float* xs = bs + N;          // K*TM (k-major)
    const int tid = threadIdx.x;
    const int T0  = blockIdx.x * TM;

    for (int i = tid; i < K * N; i += NP * MG) ws[i] = w[i];
    for (int i = tid; i < N; i += NP * MG)     bs[i] = bias[i];

    if (tid < TM) {
        const float* row = g_feat + (size_t)(T0 + tid) * K;
        float s = 0.f, s2 = 0.f;
#pragma unroll
        for (int k = 0; k < K; k++) { float v = row[k]; s += v; s2 += v * v; }
        float mu  = s * (1.0f / K);
        float var = s2 * (1.0f / K) - mu * mu;
        float rs  = rsqrtf(var + 1e-5f);
#pragma unroll
        for (int k = 0; k < K; k++)
            xs[k * TM + tid] = (row[k] - mu) * rs * gamma[k] + beta[k];
    }
    __syncthreads();

    const int n   = tid % NP;
    const int grp = tid / NP;
    if (n < N) {
        float* out = OUT_MLP ? g_mlp : g_qkv;
        const int mper = TM / MG;
        for (int m0 = grp * mper; m0 < grp * mper + mper; m0 += 4) {
            float bv = bs[n];
            float a0 = bv, a1 = bv, a2 = bv, a3 = bv;
#pragma unroll
            for (int k = 0; k < K; k++) {
                float  wv = ws[k * N + n];
                float4 xv = *(const float4*)(xs + k * TM + m0);
                a0 = fmaf(xv.x, wv, a0);
                a1 = fmaf(xv.y, wv, a1);
                a2 = fmaf(xv.z, wv, a2);
                a3 = fmaf(xv.w, wv, a3);
            }
            if (SWISH) {
                a0 = a0 / (1.f + __expf(-a0));
                a1 = a1 / (1.f + __expf(-a1));
                a2 = a2 / (1.f + __expf(-a2));
                a3 = a3 / (1.f + __expf(-a3));
            }
            size_t o = (size_t)(T0 + m0) * N + n;
            out[o]         = a0;
            out[o + N]     = a1;
            out[o + 2 * N] = a2;
            out[o + 3 * N] = a3;
        }
    }
}

// ---------------------------------------------------------------------------
// GEMM [T,K]@[K,N] + bias + residual-add into g_feat.
// IN_MLP=false -> input g_attn, true -> input g_mlp.
// ---------------------------------------------------------------------------
template <int K, int N, int NP, int MG, int TM, bool IN_MLP>
__global__ __launch_bounds__(NP * MG) void gemm_resid_k(
    const float* __restrict__ w, const float* __restrict__ bias)
{
    extern __shared__ float sm[];
    float* ws = sm;
    float* bs = sm + K * N;
    float* xs = bs + N;
    const int tid = threadIdx.x;
    const int T0  = blockIdx.x * TM;
    const float* in = IN_MLP ? g_mlp : g_attn;

    for (int i = tid; i < K * N; i += NP * MG) ws[i] = w[i];
    for (int i = tid; i < N; i += NP * MG)     bs[i] = bias[i];

    if (tid < TM) {
        const float* row = in + (size_t)(T0 + tid) * K;
#pragma unroll
        for (int k = 0; k < K; k++) xs[k * TM + tid] = row[k];
    }
    __syncthreads();

    const int n   = tid % NP;
    const int grp = tid / NP;
    if (n < N) {
        const int mper = TM / MG;
        for (int m0 = grp * mper; m0 < grp * mper + mper; m0 += 4) {
            float bv = bs[n];
            float a0 = bv, a1 = bv, a2 = bv, a3 = bv;
#pragma unroll
            for (int k = 0; k < K; k++) {
                float  wv = ws[k * N + n];
                float4 xv = *(const float4*)(xs + k * TM + m0);
                a0 = fmaf(xv.x, wv, a0);
                a1 = fmaf(xv.y, wv, a1);
                a2 = fmaf(xv.z, wv, a2);
                a3 = fmaf(xv.w, wv, a3);
            }
            size_t o = (size_t)(T0 + m0) * N + n;
            g_feat[o]         += a0;
            g_feat[o + N]     += a1;
            g_feat[o + 2 * N] += a2;
            g_feat[o + 3 * N] += a3;
        }
    }
}

// ---------------------------------------------------------------------------
// Window attention.  Block = (window, head), 256 threads = 256 queries.
// Roll handled via index arithmetic; Swin shift mask from rolled coords.
// Streaming softmax without max-subtraction (logits are tiny; masked = -100).
// ---------------------------------------------------------------------------
__global__ __launch_bounds__(256) void attn_k(int wh, int ww, int sh, int sw,
                                              int shifted)
{
    __shared__ float4 ks [256][5];
    __shared__ float4 vsm[256][5];
    __shared__ int    rg [256];

    const int n    = threadIdx.x;
    const int head = blockIdx.y;
    const int win  = blockIdx.x;
    const int nW   = Wc / ww;
    const int perB = (Hc / wh) * nW;
    const int b    = win / perB;
    const int wr_  = win % perB;
    const int wy   = wr_ / nW, wx = wr_ % nW;
    const int iy   = n / ww,   ix = n % ww;
    const int hr   = wy * wh + iy;
    const int wrr  = wx * ww + ix;
    int hs = hr + sh;  if (hs >= Hc) hs -= Hc;
    int wsv = wrr + sw; if (wsv >= Wc) wsv -= Wc;
    const size_t g = ((size_t)b * Hc + hs) * Wc + wsv;

    const float4* qp    = (const float4*)g_qkv;
    const size_t  base4 = g * 45 + (size_t)head * 5;   // 180 floats / token
    const float   scale = 0.223606797749979f;          // 20^-0.5

    float4 q[5];
#pragma unroll
    for (int i = 0; i < 5; i++) {
        float4 t = qp[base4 + i];
        t.x *= scale; t.y *= scale; t.z *= scale; t.w *= scale;
        q[i] = t;
        ks [n][i] = qp[base4 + 15 + i];
        vsm[n][i] = qp[base4 + 30 + i];
    }
    int myreg = 0;
    if (shifted) {
        int rh = (hr  < Hc - wh) ? 0 : ((hr  < Hc - sh) ? 1 : 2);
        int rw = (wrr < Wc - ww) ? 0 : ((wrr < Wc - sw) ? 1 : 2);
        myreg = rh * 3 + rw;
        rg[n] = myreg;
    }
    __syncthreads();

    float4 acc[5];
#pragma unroll
    for (int i = 0; i < 5; i++) acc[i] = make_float4(0.f, 0.f, 0.f, 0.f);
    float denom = 0.f;

    if (shifted) {
        for (int m = 0; m < 256; m++) {
            float s = 0.f;
#pragma unroll
            for (int i = 0; i < 5; i++) {
                float4 kv = ks[m][i];
                s = fmaf(q[i].x, kv.x, s); s = fmaf(q[i].y, kv.y, s);
                s = fmaf(q[i].z, kv.z, s); s = fmaf(q[i].w, kv.w, s);
            }
            if (rg[m] != myreg) s -= 100.f;
            float p = __expf(s);
            denom += p;
#pragma unroll
            for (int i = 0; i < 5; i++) {
                float4 vv = vsm[m][i];
                acc[i].x = fmaf(p, vv.x, acc[i].x);
                acc[i].y = fmaf(p, vv.y, acc[i].y);
                acc[i].z = fmaf(p, vv.z, acc[i].z);
                acc[i].w = fmaf(p, vv.w, acc[i].w);
            }
        }
    } else {
        for (int m = 0; m < 256; m++) {
            float s = 0.f;
#pragma unroll
            for (int i = 0; i < 5; i++) {
                float4 kv = ks[m][i];
                s = fmaf(q[i].x, kv.x, s); s = fmaf(q[i].y, kv.y, s);
                s = fmaf(q[i].z, kv.z, s); s = fmaf(q[i].w, kv.w, s);
            }
            float p = __expf(s);
            denom += p;
#pragma unroll
            for (int i = 0; i < 5; i++) {
                float4 vv = vsm[m][i];
                acc[i].x = fmaf(p, vv.x, acc[i].x);
                acc[i].y = fmaf(p, vv.y, acc[i].y);
                acc[i].z = fmaf(p, vv.z, acc[i].z);
                acc[i].w = fmaf(p, vv.w, acc[i].w);
            }
        }
    }

    float inv = 1.f / denom;
    float4* op = (float4*)g_attn;
    size_t  ob = g * 15 + (size_t)head * 5;     // 60 floats / token
#pragma unroll
    for (int i = 0; i < 5; i++) {
        float4 t = acc[i];
        t.x *= inv; t.y *= inv; t.z *= inv; t.w *= inv;
        op[ob + i] = t;
    }
}

// ---------------------------------------------------------------------------
// conv3x3 60->12 + PixelShuffle(2) fused.  out[b,c,2h+r1,2w+r2] = y[b,c*4+r1*2+r2,h,w]
// ---------------------------------------------------------------------------
__global__ __launch_bounds__(256) void conv_out_k(
    const float* __restrict__ lw, const float* __restrict__ lb,
    float* __restrict__ out)
{
    const int TOT = Bn * 3 * 256 * 256;
    int idx = blockIdx.x * blockDim.x + threadIdx.x;
    if (idx >= TOT) return;
    int w2 = idx & 255;
    int h2 = (idx >> 8) & 255;
    int c  = (idx >> 16) % 3;
    int bb = idx / (3 * 65536);
    int co = c * 4 + (h2 & 1) * 2 + (w2 & 1);
    int h  = h2 >> 1, w = w2 >> 1;
    float acc = lb[co];
#pragma unroll
    for (int kh = 0; kh < 3; kh++) {
        int hh = h + kh - 1;
        if ((unsigned)hh >= (unsigned)Hc) continue;
#pragma unroll
        for (int kw = 0; kw < 3; kw++) {
            int ww2 = w + kw - 1;
            if ((unsigned)ww2 >= (unsigned)Wc) continue;
            const float* fp = g_feat + ((size_t)(bb * Hc + hh) * Wc + ww2) * Cch;
            const float* wp = lw + co * (Cch * 9) + kh * 3 + kw;
#pragma unroll
            for (int ci = 0; ci < Cch; ci++)
                acc = fmaf(fp[ci], wp[ci * 9], acc);
        }
    }
    out[idx] = acc;
}

// ---------------------------------------------------------------------------
// Launch
// ---------------------------------------------------------------------------
extern "C" void kernel_launch(void* const* d_in, const int* in_sizes, int n_in,
                              void* d_out, int out_size)
{
    (void)in_sizes; (void)n_in; (void)out_size;
    const float* x      = (const float*)d_in[0];
    const float* conv_w = (const float*)d_in[1];
    const float* conv_b = (const float*)d_in[2];
    const float* ln1_g  = (const float*)d_in[3];
    const float* ln1_b  = (const float*)d_in[4];
    const float* qkv_w  = (const float*)d_in[5];
    const float* qkv_b  = (const float*)d_in[6];
    const float* proj_w = (const float*)d_in[7];
    const float* proj_b = (const float*)d_in[8];
    const float* ln2_g  = (const float*)d_in[9];
    const float* ln2_b  = (const float*)d_in[10];
    const float* fc1_w  = (const float*)d_in[11];
    const float* fc1_b  = (const float*)d_in[12];
    const float* fc2_w  = (const float*)d_in[13];
    const float* fc2_b  = (const float*)d_in[14];
    const float* last_w = (const float*)d_in[15];
    const float* last_b = (const float*)d_in[16];
    float* out = (float*)d_out;

    // smem sizes (bytes)
    constexpr int SM_QKV  = (60 * 180 + 180 + 60 * 64)  * 4;  // 59280
    constexpr int SM_FC1  = (60 * 120 + 120 + 60 * 64)  * 4;  // 44640
    constexpr int SM_PROJ = (60 * 60  + 60  + 60 * 128) * 4;  // 45360
    constexpr int SM_FC2  = (120 * 60 + 60  + 120 * 64) * 4;  // 59760

    cudaFuncSetAttribute(ln_gemm_k<60, 180, 192, 2, 64, false, false>,
                         cudaFuncAttributeMaxDynamicSharedMemorySize, SM_QKV);
    cudaFuncSetAttribute(ln_gemm_k<60, 120, 128, 2, 64, true, true>,
                         cudaFuncAttributeMaxDynamicSharedMemorySize, SM_FC1);
    cudaFuncSetAttribute(gemm_resid_k<60, 60, 64, 4, 128, false>,
                         cudaFuncAttributeMaxDynamicSharedMemorySize, SM_PROJ);
    cudaFuncSetAttribute(gemm_resid_k<120, 60, 64, 4, 64, true>,
                         cudaFuncAttributeMaxDynamicSharedMemorySize, SM_FC2);

    conv_in_k<<<(NTOK * Cch + 255) / 256, 256>>>(x, conv_w, conv_b);

    for (int l = 0; l < NL; l++) {
        int i  = l % 6;
        int wi = i % 2;
        int wh = wi ? 8 : 32;
        int ww = wi ? 32 : 8;
        int shifted = (i % 4) >= 2;
        int sh = shifted ? (wi ? 4 : 16) : 0;
        int sw = shifted ? (wi ? 16 : 4) : 0;

        ln_gemm_k<60, 180, 192, 2, 64, false, false>
            <<<NTOK / 64, 384, SM_QKV>>>(ln1_g + l * 60, ln1_b + l * 60,
                                         qkv_w + (size_t)l * 60 * 180,
                                         qkv_b + l * 180);

        attn_k<<<dim3(Bn * 64, NHEADS), 256>>>(wh, ww, sh, sw, shifted);

        gemm_resid_k<60, 60, 64, 4, 128, false>
            <<<NTOK / 128, 256, SM_PROJ>>>(proj_w + (size_t)l * 3600,
                                           proj_b + l * 60);

        ln_gemm_k<60, 120, 128, 2, 64, true, true>
            <<<NTOK / 64, 256, SM_FC1>>>(ln2_g + l * 60, ln2_b + l * 60,
                                         fc1_w + (size_t)l * 7200,
                                         fc1_b + l * 120);

        gemm_resid_k<120, 60, 64, 4, 64, true>
            <<<NTOK / 64, 256, SM_FC2>>>(fc2_w + (size_t)l * 7200,
                                         fc2_b + l * 60);
    }

    conv_out_k<<<(Bn * 3 * 256 * 256 + 255) / 256, 256>>>(last_w, last_b, out);
}